// round 2
// baseline (speedup 1.0000x reference)
#include <cuda_runtime.h>

// Lifting wavelet forward transform, v2: vectorized, halo'd half-row CTAs.
// input: (4096, 8192) f32. even = in[:, ::2], odd = in[:, 1::2] (4096 each).
// wavelet[j] = scaling_rec[7-j] * (j odd ? -1 : +1)
// odd_out[k]  = odd[k]  - sum_j wavelet[j] * even[(k-j) mod 4096]
// even_out[k] = even[k] - sum_j scaling[j] * odd[(k-j) mod 4096]
// Output: [even_updated | odd_updated], each 4096x4096 f32.
//
// CTA = half a row (2048 pairs) + 8-pair circular halo -> no masking in compute.
// All shared traffic is LDS.128/STS.64; global is LDG.128/STG.128.

#define ROWS    4096
#define ROWLEN  8192
#define HALF    4096
#define HALFSEG 2048          // pairs per CTA
#define NTH     512
#define HALO    8

__global__ __launch_bounds__(NTH, 2)
void wavelet_fwd_v2(const float* __restrict__ in,
                    const float* __restrict__ scaling,
                    const float* __restrict__ scaling_rec,
                    float* __restrict__ out)
{
    __shared__ float sE[HALFSEG + HALO];   // [0..7] halo, [8..2055] main
    __shared__ float sO[HALFSEG + HALO];
    __shared__ float fWav[8];
    __shared__ float fScl[8];

    const int t    = threadIdx.x;
    const int row  = blockIdx.x >> 1;
    const int half = blockIdx.x & 1;

    if (t < 8) {
        fScl[t] = scaling[t];
        float w = scaling_rec[7 - t];
        fWav[t] = (t & 1) ? -w : w;
    }

    const float* rowp = in + (size_t)row * ROWLEN;

    // Main segment: 2048 pairs = 4096 floats = 1024 float4 (interleaved e,o,e,o).
    const float4* seg = reinterpret_cast<const float4*>(rowp + half * HALF);
#pragma unroll
    for (int s = 0; s < 2; s++) {
        int i = t + s * NTH;              // float4 index, i < 1024
        float4 v = seg[i];
        // float4 i covers pairs 2i, 2i+1
        float2* e2 = reinterpret_cast<float2*>(&sE[HALO + 2 * i]);
        float2* o2 = reinterpret_cast<float2*>(&sO[HALO + 2 * i]);
        *e2 = make_float2(v.x, v.z);
        *o2 = make_float2(v.y, v.w);
    }

    // Halo: previous 8 pairs = previous 16 floats of the row (circular).
    // half=0 -> floats 8176..8191 ; half=1 -> floats 4080..4095. No wrap inside.
    if (t < 4) {
        int base = (half * HALF - 16 + ROWLEN) & (ROWLEN - 1);
        float4 v = *reinterpret_cast<const float4*>(rowp + base + 4 * t);
        float2* e2 = reinterpret_cast<float2*>(&sE[2 * t]);
        float2* o2 = reinterpret_cast<float2*>(&sO[2 * t]);
        *e2 = make_float2(v.x, v.z);
        *o2 = make_float2(v.y, v.w);
    }
    __syncthreads();

    const float w0 = fWav[0], w1 = fWav[1], w2 = fWav[2], w3 = fWav[3];
    const float w4 = fWav[4], w5 = fWav[5], w6 = fWav[6], w7 = fWav[7];
    const float c0 = fScl[0], c1 = fScl[1], c2 = fScl[2], c3 = fScl[3];
    const float c4 = fScl[4], c5 = fScl[5], c6 = fScl[6], c7 = fScl[7];

    // Thread t computes 4 consecutive pairs, local lk0 = 4t.
    const int lk0 = 4 * t;

    // Window: shared float indices [lk0, lk0+12) == pairs lk0-8 .. lk0+3.
    float e[12], o[12];
#pragma unroll
    for (int q = 0; q < 3; q++) {
        float4 ve = *reinterpret_cast<const float4*>(&sE[lk0 + 4 * q]);
        float4 vo = *reinterpret_cast<const float4*>(&sO[lk0 + 4 * q]);
        e[4*q+0] = ve.x; e[4*q+1] = ve.y; e[4*q+2] = ve.z; e[4*q+3] = ve.w;
        o[4*q+0] = vo.x; o[4*q+1] = vo.y; o[4*q+2] = vo.z; o[4*q+3] = vo.w;
    }

    float rE[4], rO[4];
#pragma unroll
    for (int m = 0; m < 4; m++) {
        // e[m+8] is pair (lk0+m); e[m+8-j] is pair (lk0+m-j)
        float ce = w0*e[m+8] + w1*e[m+7] + w2*e[m+6] + w3*e[m+5]
                 + w4*e[m+4] + w5*e[m+3] + w6*e[m+2] + w7*e[m+1];
        float co = c0*o[m+8] + c1*o[m+7] + c2*o[m+6] + c3*o[m+5]
                 + c4*o[m+4] + c5*o[m+3] + c6*o[m+2] + c7*o[m+1];
        rO[m] = o[m+8] - ce;   // odd  - conv(even, wavelet)
        rE[m] = e[m+8] - co;   // even - conv(odd,  scaling)
    }

    const size_t obase = (size_t)row * HALF + half * HALFSEG + lk0;
    float4* pe = reinterpret_cast<float4*>(out + obase);
    float4* po = reinterpret_cast<float4*>(out + (size_t)ROWS * HALF + obase);
    *pe = make_float4(rE[0], rE[1], rE[2], rE[3]);
    *po = make_float4(rO[0], rO[1], rO[2], rO[3]);
}

extern "C" void kernel_launch(void* const* d_in, const int* in_sizes, int n_in,
                              void* d_out, int out_size)
{
    const float* input       = (const float*)d_in[0];
    const float* scaling     = (const float*)d_in[1];
    const float* scaling_rec = (const float*)d_in[2];
    float* out = (float*)d_out;

    wavelet_fwd_v2<<<ROWS * 2, NTH>>>(input, scaling, scaling_rec, out);
}

// round 3
// speedup vs baseline: 1.3011x; 1.3011x over previous
#include <cuda_runtime.h>

// Lifting wavelet forward transform, v3: barrier-free, pure-LDG streaming.
// input: (4096, 8192) f32. even = in[:, ::2], odd = in[:, 1::2] (4096 each).
// wavelet[j] = scaling_rec[7-j] * (j odd ? -1 : +1)
// odd_out[k]  = odd[k]  - sum_j wavelet[j] * even[(k-j) mod 4096]
// even_out[k] = even[k] - sum_j scaling[j] * odd[(k-j) mod 4096]
// Output: [even_updated | odd_updated], each 4096x4096 f32.
//
// Each thread owns 4 consecutive pairs. It loads its 24-float input window
// (floats 2k0-16 .. 2k0+7 of the row, circular) as 6 aligned float4 LDGs with
// per-float4 wrap masking. No shared memory, no __syncthreads -> loads from
// many warps stay in flight continuously (no bursty phase structure).

#define ROWS    4096
#define ROWLEN  8192
#define HALF    4096
#define NTH     256
#define FMASK   (ROWLEN - 1)

__constant__ float cScaling[8];
__constant__ float cRec[8];

__global__ __launch_bounds__(NTH)
void wavelet_fwd_v3(const float* __restrict__ in,
                    float* __restrict__ out)
{
    const int g   = blockIdx.x * NTH + threadIdx.x;  // 0 .. 4M-1
    const int row = g >> 10;                          // 1024 threads per row
    const int lk  = (g & 1023) << 2;                  // pair base: 0..4092

    const float* rowp = in + (size_t)row * ROWLEN;

    // Window: input floats (2*lk - 16 + i) mod 8192, i = 0..23.
    // 6 aligned float4 loads, circular via & FMASK (offsets stay 16B-aligned).
    float wnd[24];
#pragma unroll
    for (int q = 0; q < 6; q++) {
        int fi = (2 * lk - 16 + 4 * q) & FMASK;
        float4 v = *reinterpret_cast<const float4*>(rowp + fi);
        wnd[4*q+0] = v.x; wnd[4*q+1] = v.y; wnd[4*q+2] = v.z; wnd[4*q+3] = v.w;
    }

    // Taps from constant memory (LDC, uniform, no L1tex traffic).
    float w0 = cRec[7], w1 = -cRec[6], w2 = cRec[5], w3 = -cRec[4];
    float w4 = cRec[3], w5 = -cRec[2], w6 = cRec[1], w7 = -cRec[0];
    float c0 = cScaling[0], c1 = cScaling[1], c2 = cScaling[2], c3 = cScaling[3];
    float c4 = cScaling[4], c5 = cScaling[5], c6 = cScaling[6], c7 = cScaling[7];

    // e[j] = pair (lk-8+j) even value = wnd[2j]; o[j] = wnd[2j+1], j = 0..11.
    float rE[4], rO[4];
#pragma unroll
    for (int m = 0; m < 4; m++) {
        // pair (lk+m) corresponds to j = m+8
        float e8 = wnd[2*(m+8)],   o8 = wnd[2*(m+8)+1];
        float ce = w0*e8
                 + w1*wnd[2*(m+7)]   + w2*wnd[2*(m+6)]   + w3*wnd[2*(m+5)]
                 + w4*wnd[2*(m+4)]   + w5*wnd[2*(m+3)]   + w6*wnd[2*(m+2)]
                 + w7*wnd[2*(m+1)];
        float co = c0*o8
                 + c1*wnd[2*(m+7)+1] + c2*wnd[2*(m+6)+1] + c3*wnd[2*(m+5)+1]
                 + c4*wnd[2*(m+4)+1] + c5*wnd[2*(m+3)+1] + c6*wnd[2*(m+2)+1]
                 + c7*wnd[2*(m+1)+1];
        rO[m] = o8 - ce;   // odd  - conv(even, wavelet)
        rE[m] = e8 - co;   // even - conv(odd,  scaling)
    }

    const size_t obase = (size_t)row * HALF + lk;
    *reinterpret_cast<float4*>(out + obase) =
        make_float4(rE[0], rE[1], rE[2], rE[3]);
    *reinterpret_cast<float4*>(out + (size_t)ROWS * HALF + obase) =
        make_float4(rO[0], rO[1], rO[2], rO[3]);
}

extern "C" void kernel_launch(void* const* d_in, const int* in_sizes, int n_in,
                              void* d_out, int out_size)
{
    const float* input = (const float*)d_in[0];
    float* out = (float*)d_out;

    // Capturable D2D copies into constant memory (memcpy nodes, no alloc).
    cudaMemcpyToSymbolAsync(cScaling, d_in[1], 8 * sizeof(float), 0,
                            cudaMemcpyDeviceToDevice, 0);
    cudaMemcpyToSymbolAsync(cRec, d_in[2], 8 * sizeof(float), 0,
                            cudaMemcpyDeviceToDevice, 0);

    const int total_threads = ROWS * (HALF / 4);       // 4M
    wavelet_fwd_v3<<<total_threads / NTH, NTH>>>(input, out);
}